// round 12
// baseline (speedup 1.0000x reference)
#include <cuda_runtime.h>
#include <math.h>
#include <limits.h>

#define HDIM 128
#define SDIM 32
#define KTOP 8
#define RPB  512                  // rows per K1 block

// Scratch (__device__ globals; no allocation allowed)
__device__ float2 g_cand[256 * KTOP];     // (value, index bits); 196 blocks used

__device__ __forceinline__ bool better(float va, int ia, float vb, int ib) {
    // jax.lax.top_k ordering: higher value first, ties -> lower index
    return (va > vb) || (va == vb && ia < ib);
}

// compare-exchange: keep the better in (va,ia)
__device__ __forceinline__ void ce(float& va, int& ia, float& vb, int& ib) {
    if (better(vb, ib, va, ia)) {
        float tv = va; va = vb; vb = tv;
        int   ti = ia; ia = ib; ib = ti;
    }
}

// Merge two sorted-descending 8-lists into lv/li (top-8 of union).
// m[i] = better(A[i], B[7-i]) gives the top-8 multiset as a bitonic sequence;
// fixed bitonic network (distances 4,2,1) sorts it. All constant indices.
__device__ __forceinline__ void merge8(float* lv, int* li,
                                       const float* pv, const int* pi) {
    float mv[8]; int mi[8];
#pragma unroll
    for (int i = 0; i < 8; ++i) {
        if (better(lv[i], li[i], pv[7 - i], pi[7 - i])) { mv[i] = lv[i]; mi[i] = li[i]; }
        else                                            { mv[i] = pv[7 - i]; mi[i] = pi[7 - i]; }
    }
    ce(mv[0], mi[0], mv[4], mi[4]); ce(mv[1], mi[1], mv[5], mi[5]);
    ce(mv[2], mi[2], mv[6], mi[6]); ce(mv[3], mi[3], mv[7], mi[7]);
    ce(mv[0], mi[0], mv[2], mi[2]); ce(mv[1], mi[1], mv[3], mi[3]);
    ce(mv[4], mi[4], mv[6], mi[6]); ce(mv[5], mi[5], mv[7], mi[7]);
    ce(mv[0], mi[0], mv[1], mi[1]); ce(mv[2], mi[2], mv[3], mi[3]);
    ce(mv[4], mi[4], mv[5], mi[5]); ce(mv[6], mi[6], mv[7], mi[7]);
#pragma unroll
    for (int i = 0; i < 8; ++i) { lv[i] = mv[i]; li[i] = mi[i]; }
}

// Butterfly-reduce sorted 8-lists across lanes 0..2*maxoff-1 (register shuffles only).
template <int MAXOFF>
__device__ __forceinline__ void warp_merge_levels(float* lv, int* li) {
#pragma unroll
    for (int o = 1; o <= MAXOFF; o <<= 1) {
        float pv[8]; int pi[8];
#pragma unroll
        for (int j = 0; j < 8; ++j) {
            pv[j] = __shfl_xor_sync(0xffffffffu, lv[j], o);
            pi[j] = __shfl_xor_sync(0xffffffffu, li[j], o);
        }
        merge8(lv, li, pv, pi);
    }
}

__device__ __forceinline__ void insert_topk(float* lv, int* li, float v, int c) {
    if (better(v, c, lv[KTOP - 1], li[KTOP - 1])) {
        int j = KTOP - 1;
#pragma unroll
        for (; j > 0; --j) {
            if (better(v, c, lv[j - 1], li[j - 1])) {
                lv[j] = lv[j - 1];
                li[j] = li[j - 1];
            } else break;
        }
        lv[j] = v;
        li[j] = c;
    }
}

// ---------------------------------------------------------------------------
// K1: cosine sims (coalesced warp-per-row, 64 rows/warp) + block top-8 via
// register bitonic merges (no smem tree).
// ---------------------------------------------------------------------------
__global__ void __launch_bounds__(256)
sims_topk(const float* __restrict__ q,
          const float* __restrict__ emb,
          int C) {
    __shared__ float sq[HDIM];
    __shared__ float s_rqn;
    __shared__ float s_sims[RPB];
    __shared__ float swv[8 * KTOP];
    __shared__ int   swi[8 * KTOP];

    const int t    = threadIdx.x;
    const int lane = t & 31;
    const int w    = t >> 5;

    if (t < HDIM) sq[t] = q[t];               // query row 0
    __syncthreads();
    if (t < 32) {
        const float4 a = reinterpret_cast<const float4*>(sq)[t];
        float s = a.x * a.x + a.y * a.y + a.z * a.z + a.w * a.w;
#pragma unroll
        for (int o = 16; o; o >>= 1) s += __shfl_xor_sync(0xffffffffu, s, o);
        if (t == 0) s_rqn = 1.0f / fmaxf(sqrtf(s), 1e-8f);
    }
    __syncthreads();
    const float rqn = s_rqn;
    const float4 q4 = reinterpret_cast<const float4*>(sq)[lane];

    const float4* __restrict__ emb4 = reinterpret_cast<const float4*>(emb);
    const int base = blockIdx.x * RPB;

    // Each warp streams 64 rows: 16 iterations of 4 front-batched coalesced loads.
#pragma unroll 4
    for (int it = 0; it < 16; ++it) {
        const int loc0 = w * 64 + it * 4;
        float4 ev[4];
#pragma unroll
        for (int j = 0; j < 4; ++j) {
            const int r = min(base + loc0 + j, C - 1);
            ev[j] = emb4[(size_t)r * (HDIM / 4) + lane];
        }
        float dot[4], esq[4];
#pragma unroll
        for (int j = 0; j < 4; ++j) {
            dot[j] = ev[j].x * q4.x + ev[j].y * q4.y + ev[j].z * q4.z + ev[j].w * q4.w;
            esq[j] = ev[j].x * ev[j].x + ev[j].y * ev[j].y + ev[j].z * ev[j].z + ev[j].w * ev[j].w;
        }
#pragma unroll
        for (int o = 16; o; o >>= 1) {
#pragma unroll
            for (int j = 0; j < 4; ++j) {
                dot[j] += __shfl_xor_sync(0xffffffffu, dot[j], o);
                esq[j] += __shfl_xor_sync(0xffffffffu, esq[j], o);
            }
        }
        if (lane < 4) {
            const int r = base + loc0 + lane;
            s_sims[loc0 + lane] = (r < C)
                ? dot[lane] * rqn / fmaxf(sqrtf(esq[lane]), 1e-8f)
                : -INFINITY;
        }
    }
    __syncthreads();

    // ---- block top-8 of 512 sims: 2 sims/thread -> shfl bitonic reduce ----
    float lv[KTOP]; int li[KTOP];
    {
        const float s0 = s_sims[2 * t];     const int i0 = base + 2 * t;
        const float s1 = s_sims[2 * t + 1]; const int i1 = base + 2 * t + 1;
        if (better(s1, i1, s0, i0)) { lv[0] = s1; li[0] = i1; lv[1] = s0; li[1] = i0; }
        else                        { lv[0] = s0; li[0] = i0; lv[1] = s1; li[1] = i1; }
#pragma unroll
        for (int j = 2; j < KTOP; ++j) { lv[j] = -INFINITY; li[j] = INT_MAX; }
    }
    warp_merge_levels<16>(lv, li);            // 5 shfl levels -> warp top-8
    if (lane == 0) {
#pragma unroll
        for (int j = 0; j < KTOP; ++j) { swv[w * KTOP + j] = lv[j]; swi[w * KTOP + j] = li[j]; }
    }
    __syncthreads();
    if (t < 32) {
        float fv[KTOP]; int fi[KTOP];
        if (lane < 8) {
#pragma unroll
            for (int j = 0; j < KTOP; ++j) { fv[j] = swv[lane * KTOP + j]; fi[j] = swi[lane * KTOP + j]; }
        } else {
#pragma unroll
            for (int j = 0; j < KTOP; ++j) { fv[j] = -INFINITY; fi[j] = INT_MAX; }
        }
        warp_merge_levels<4>(fv, fi);          // 3 shfl levels -> block top-8
        if (lane == 0) {
#pragma unroll
            for (int j = 0; j < KTOP; ++j)
                g_cand[blockIdx.x * KTOP + j] = make_float2(fv[j], __int_as_float(fi[j]));
        }
    }
}

// ---------------------------------------------------------------------------
// K2: merge ncand candidates (register bitonic, no smem tree) -> top-8,
// gather episodes, write scores. One block, 1024 threads.
// ---------------------------------------------------------------------------
__global__ void __launch_bounds__(1024)
final_gather(const float* __restrict__ episodes,
             float* __restrict__ out,
             int ncand) {
    __shared__ float swv[8 * KTOP];
    __shared__ int   swi[8 * KTOP];
    __shared__ float s_tv[KTOP];
    __shared__ int   s_ti[KTOP];

    const int t    = threadIdx.x;
    const int lane = t & 31;
    const int w    = t >> 5;

    if (t < 256) {
        // 7 unconditional front-batched LDG.64 (clamped address, patched value).
        float2 cd[7];
#pragma unroll
        for (int r = 0; r < 7; ++r) {
            const int c = t + r * 256;
            cd[r] = g_cand[min(c, ncand - 1)];
            if (c >= ncand) cd[r] = make_float2(-INFINITY, __int_as_float(INT_MAX));
        }
        float lv[KTOP]; int li[KTOP];
#pragma unroll
        for (int j = 0; j < KTOP; ++j) { lv[j] = -INFINITY; li[j] = INT_MAX; }
#pragma unroll
        for (int r = 0; r < 7; ++r)
            insert_topk(lv, li, cd[r].x, __float_as_int(cd[r].y));

        warp_merge_levels<16>(lv, li);         // 5 shfl levels -> warp top-8
        if (lane == 0 && w < 8) {
#pragma unroll
            for (int j = 0; j < KTOP; ++j) { swv[w * KTOP + j] = lv[j]; swi[w * KTOP + j] = li[j]; }
        }
    }
    __syncthreads();

    if (t < 32) {
        float fv[KTOP]; int fi[KTOP];
        if (lane < 8) {
#pragma unroll
            for (int j = 0; j < KTOP; ++j) { fv[j] = swv[lane * KTOP + j]; fi[j] = swi[lane * KTOP + j]; }
        } else {
#pragma unroll
            for (int j = 0; j < KTOP; ++j) { fv[j] = -INFINITY; fi[j] = INT_MAX; }
        }
        warp_merge_levels<4>(fv, fi);          // 3 shfl levels -> global top-8
        if (lane == 0) {
#pragma unroll
            for (int j = 0; j < KTOP; ++j) { s_tv[j] = fv[j]; s_ti[j] = fi[j]; }
        }
    }
    __syncthreads();

    // ---- gather 8 episodes [8,32,128]: thread t = float4 column t, 8 loads ----
    int idx[KTOP];
#pragma unroll
    for (int e = 0; e < KTOP; ++e) idx[e] = s_ti[e];

    const float4* __restrict__ epi4 = reinterpret_cast<const float4*>(episodes);
    float4* __restrict__ out4 = reinterpret_cast<float4*>(out);
    const int EP4 = SDIM * HDIM / 4;           // 1024 float4 per episode
    float4 vals[KTOP];
#pragma unroll
    for (int e = 0; e < KTOP; ++e)
        vals[e] = epi4[(size_t)idx[e] * EP4 + t];
#pragma unroll
    for (int e = 0; e < KTOP; ++e)
        out4[e * EP4 + t] = vals[e];

    if (t < KTOP)
        out[KTOP * SDIM * HDIM + t] = s_tv[t]; // top_scores[0]
}

extern "C" void kernel_launch(void* const* d_in, const int* in_sizes, int n_in,
                              void* d_out, int out_size) {
    const float* query    = (const float*)d_in[0];  // [B, 128]
    const float* episodes = (const float*)d_in[1];  // [C, 32, 128]
    const float* emb      = (const float*)d_in[2];  // [C, 128]
    (void)n_in; (void)out_size;

    const int C    = in_sizes[2] / HDIM;            // 100000
    const int nblk = (C + RPB - 1) / RPB;           // 196

    sims_topk<<<nblk, 256>>>(query, emb, C);
    final_gather<<<1, 1024>>>(episodes, (float*)d_out, nblk * KTOP);
}

// round 13
// speedup vs baseline: 1.2675x; 1.2675x over previous
#include <cuda_runtime.h>
#include <math.h>
#include <limits.h>

#define HDIM 128
#define SDIM 32
#define KTOP 8
#define NB1  128      // stage-1 top-k blocks
#define RPW  8        // rows per warp in sims (front-batched)

// Scratch (__device__ globals; no allocation allowed)
__device__ float g_sims[100096];          // padded past C
__device__ float g_cand_v[NB1 * KTOP];
__device__ int   g_cand_i[NB1 * KTOP];
__device__ float g_top_v[KTOP];
__device__ int   g_top_i[KTOP];

__device__ __forceinline__ bool better(float va, int ia, float vb, int ib) {
    // jax.lax.top_k ordering: higher value first, ties -> lower index
    return (va > vb) || (va == vb && ia < ib);
}

__device__ __forceinline__ void insert_topk(float* lv, int* li, float v, int c) {
    if (better(v, c, lv[KTOP - 1], li[KTOP - 1])) {
        int j = KTOP - 1;
#pragma unroll
        for (; j > 0; --j) {
            if (better(v, c, lv[j - 1], li[j - 1])) {
                lv[j] = lv[j - 1];
                li[j] = li[j - 1];
            } else break;
        }
        lv[j] = v;
        li[j] = c;
    }
}

// Shared-memory merge tree: 256 sorted top-8 lists -> slot 0 holds block top-8.
__device__ __forceinline__ void block_merge_topk(float* sv, int* si) {
    const int t = threadIdx.x;
    for (int s = 128; s > 0; s >>= 1) {
        if (t < s) {
            float mv[KTOP]; int mi[KTOP];
            int a = 0, b = 0;
#pragma unroll
            for (int j = 0; j < KTOP; ++j) {
                const float va = sv[t * KTOP + a];       const int ia = si[t * KTOP + a];
                const float vb = sv[(t + s) * KTOP + b]; const int ib = si[(t + s) * KTOP + b];
                if (better(va, ia, vb, ib)) { mv[j] = va; mi[j] = ia; ++a; }
                else                        { mv[j] = vb; mi[j] = ib; ++b; }
            }
#pragma unroll
            for (int j = 0; j < KTOP; ++j) { sv[t * KTOP + j] = mv[j]; si[t * KTOP + j] = mi[j]; }
        }
        __syncthreads();
    }
}

// ---------------------------------------------------------------------------
// Kernel 1: cosine sims, warp-per-row, 8 rows per warp, ALL 8 coalesced
// LDG.128 front-batched (8 in flight per lane). __launch_bounds__(256,4)
// grants 64 regs so ptxas keeps the batch live.
// ---------------------------------------------------------------------------
__global__ void __launch_bounds__(256, 4)
sims_kernel(const float* __restrict__ q,
            const float* __restrict__ emb,
            int C) {
    __shared__ float sq[HDIM];
    __shared__ float s_rqn;
    const int t    = threadIdx.x;
    const int lane = t & 31;

    if (t < HDIM) sq[t] = q[t];               // query row 0
    __syncthreads();
    if (t < 32) {
        const float4 a = reinterpret_cast<const float4*>(sq)[t];
        float s = a.x * a.x + a.y * a.y + a.z * a.z + a.w * a.w;
#pragma unroll
        for (int o = 16; o; o >>= 1) s += __shfl_xor_sync(0xffffffffu, s, o);
        if (t == 0) s_rqn = 1.0f / fmaxf(sqrtf(s), 1e-8f);
    }
    __syncthreads();
    const float rqn = s_rqn;
    const float4 q4 = reinterpret_cast<const float4*>(sq)[lane];

    const int warp = blockIdx.x * (blockDim.x >> 5) + (t >> 5);
    const int r0   = warp * RPW;              // first row of this warp
    const float4* __restrict__ emb4 = reinterpret_cast<const float4*>(emb);

    // Front-batched coalesced loads: 8 independent warp-wide 512B reads.
    float4 ev[RPW];
#pragma unroll
    for (int j = 0; j < RPW; ++j) {
        const int r = min(r0 + j, C - 1);     // clamp; store is guarded
        ev[j] = emb4[(size_t)r * (HDIM / 4) + lane];
    }

    float dot[RPW], esq[RPW];
#pragma unroll
    for (int j = 0; j < RPW; ++j) {
        dot[j] = ev[j].x * q4.x + ev[j].y * q4.y + ev[j].z * q4.z + ev[j].w * q4.w;
        esq[j] = ev[j].x * ev[j].x + ev[j].y * ev[j].y + ev[j].z * ev[j].z + ev[j].w * ev[j].w;
    }
    // Interleaved butterflies: 16 independent shfl chains -> high ILP.
#pragma unroll
    for (int o = 16; o; o >>= 1) {
#pragma unroll
        for (int j = 0; j < RPW; ++j) {
            dot[j] += __shfl_xor_sync(0xffffffffu, dot[j], o);
            esq[j] += __shfl_xor_sync(0xffffffffu, esq[j], o);
        }
    }

    if (lane < RPW) {
        const int r = r0 + lane;
        if (r < C)
            g_sims[r] = dot[lane] * rqn / fmaxf(sqrtf(esq[lane]), 1e-8f);
    }
}

// ---------------------------------------------------------------------------
// Kernel 2: stage-1 top-8. 128 blocks grid-stride over g_sims.
// ---------------------------------------------------------------------------
__global__ void topk_stage1(int C) {
    __shared__ float sv[256 * KTOP];
    __shared__ int   si[256 * KTOP];
    const int t = threadIdx.x;

    float lv[KTOP]; int li[KTOP];
#pragma unroll
    for (int j = 0; j < KTOP; ++j) { lv[j] = -INFINITY; li[j] = INT_MAX; }

    for (int c = blockIdx.x * blockDim.x + t; c < C; c += gridDim.x * blockDim.x)
        insert_topk(lv, li, g_sims[c], c);

#pragma unroll
    for (int j = 0; j < KTOP; ++j) { sv[t * KTOP + j] = lv[j]; si[t * KTOP + j] = li[j]; }
    __syncthreads();
    block_merge_topk(sv, si);

    if (t < KTOP) {
        g_cand_v[blockIdx.x * KTOP + t] = sv[t];
        g_cand_i[blockIdx.x * KTOP + t] = si[t];
    }
}

// ---------------------------------------------------------------------------
// Kernel 3: merge 1024 candidates -> global top-8; write scores into out.
// ---------------------------------------------------------------------------
__global__ void topk_final(float* __restrict__ out) {
    __shared__ float sv[256 * KTOP];
    __shared__ int   si[256 * KTOP];
    const int t = threadIdx.x;

    float lv[KTOP]; int li[KTOP];
#pragma unroll
    for (int j = 0; j < KTOP; ++j) { lv[j] = -INFINITY; li[j] = INT_MAX; }

    for (int c = t; c < NB1 * KTOP; c += 256)
        insert_topk(lv, li, g_cand_v[c], g_cand_i[c]);

#pragma unroll
    for (int j = 0; j < KTOP; ++j) { sv[t * KTOP + j] = lv[j]; si[t * KTOP + j] = li[j]; }
    __syncthreads();
    block_merge_topk(sv, si);

    if (t < KTOP) {
        g_top_v[t] = sv[t];
        g_top_i[t] = si[t];
        out[KTOP * SDIM * HDIM + t] = sv[t];   // top_scores[0]
    }
}

// ---------------------------------------------------------------------------
// Kernel 4: gather top-8 episodes [8,32,128]; 8 blocks per episode.
// ---------------------------------------------------------------------------
__global__ void gather_kernel(const float* __restrict__ episodes,
                              float* __restrict__ out) {
    const int e    = blockIdx.x >> 3;
    const int part = blockIdx.x & 7;
    const int idx  = g_top_i[e];

    const int per = (SDIM * HDIM / 4) / 8;    // 128 float4 per block
    const float4* __restrict__ src =
        reinterpret_cast<const float4*>(episodes + (size_t)idx * (SDIM * HDIM)) + part * per;
    float4* __restrict__ dst =
        reinterpret_cast<float4*>(out + (size_t)e * (SDIM * HDIM)) + part * per;

    if (threadIdx.x < per) dst[threadIdx.x] = src[threadIdx.x];
}

extern "C" void kernel_launch(void* const* d_in, const int* in_sizes, int n_in,
                              void* d_out, int out_size) {
    const float* query    = (const float*)d_in[0];  // [B, 128]
    const float* episodes = (const float*)d_in[1];  // [C, 32, 128]
    const float* emb      = (const float*)d_in[2];  // [C, 128]
    (void)n_in; (void)out_size;

    const int C = in_sizes[2] / HDIM;               // 100000

    // warp handles RPW rows; 8 warps per block
    const int nwarps  = (C + RPW - 1) / RPW;        // 12500
    const int blocksA = (nwarps + 7) / 8;           // 1563
    sims_kernel<<<blocksA, 256>>>(query, emb, C);
    topk_stage1<<<NB1, 256>>>(C);
    topk_final<<<1, 256>>>((float*)d_out);
    gather_kernel<<<64, 128>>>(episodes, (float*)d_out);
}

// round 14
// speedup vs baseline: 1.3505x; 1.0654x over previous
#include <cuda_runtime.h>
#include <math.h>
#include <limits.h>

#define HDIM 128
#define SDIM 32
#define KTOP 8
#define NB1  128      // stage-1 top-k blocks
#define RPW  8        // rows per warp in sims (front-batched)

// Scratch (__device__ globals; no allocation allowed)
__device__ float g_sims[100096];          // padded past C
__device__ float g_cand_v[NB1 * KTOP];
__device__ int   g_cand_i[NB1 * KTOP];
__device__ float g_top_v[KTOP];
__device__ int   g_top_i[KTOP];

__device__ __forceinline__ bool better(float va, int ia, float vb, int ib) {
    // jax.lax.top_k ordering: higher value first, ties -> lower index
    return (va > vb) || (va == vb && ia < ib);
}

__device__ __forceinline__ void insert_topk(float* lv, int* li, float v, int c) {
    if (better(v, c, lv[KTOP - 1], li[KTOP - 1])) {
        int j = KTOP - 1;
#pragma unroll
        for (; j > 0; --j) {
            if (better(v, c, lv[j - 1], li[j - 1])) {
                lv[j] = lv[j - 1];
                li[j] = li[j - 1];
            } else break;
        }
        lv[j] = v;
        li[j] = c;
    }
}

// Shared-memory merge tree: 256 sorted top-8 lists -> slot 0 holds block top-8.
__device__ __forceinline__ void block_merge_topk(float* sv, int* si) {
    const int t = threadIdx.x;
    for (int s = 128; s > 0; s >>= 1) {
        if (t < s) {
            float mv[KTOP]; int mi[KTOP];
            int a = 0, b = 0;
#pragma unroll
            for (int j = 0; j < KTOP; ++j) {
                const float va = sv[t * KTOP + a];       const int ia = si[t * KTOP + a];
                const float vb = sv[(t + s) * KTOP + b]; const int ib = si[(t + s) * KTOP + b];
                if (better(va, ia, vb, ib)) { mv[j] = va; mi[j] = ia; ++a; }
                else                        { mv[j] = vb; mi[j] = ib; ++b; }
            }
#pragma unroll
            for (int j = 0; j < KTOP; ++j) { sv[t * KTOP + j] = mv[j]; si[t * KTOP + j] = mi[j]; }
        }
        __syncthreads();
    }
}

// ---------------------------------------------------------------------------
// Kernel 1: cosine sims, warp-per-row, 8 rows per warp, all 8 coalesced
// LDG.128 front-batched. (Identical to R13.)
// ---------------------------------------------------------------------------
__global__ void __launch_bounds__(256, 4)
sims_kernel(const float* __restrict__ q,
            const float* __restrict__ emb,
            int C) {
    __shared__ float sq[HDIM];
    __shared__ float s_rqn;
    const int t    = threadIdx.x;
    const int lane = t & 31;

    if (t < HDIM) sq[t] = q[t];               // query row 0
    __syncthreads();
    if (t < 32) {
        const float4 a = reinterpret_cast<const float4*>(sq)[t];
        float s = a.x * a.x + a.y * a.y + a.z * a.z + a.w * a.w;
#pragma unroll
        for (int o = 16; o; o >>= 1) s += __shfl_xor_sync(0xffffffffu, s, o);
        if (t == 0) s_rqn = 1.0f / fmaxf(sqrtf(s), 1e-8f);
    }
    __syncthreads();
    const float rqn = s_rqn;
    const float4 q4 = reinterpret_cast<const float4*>(sq)[lane];

    const int warp = blockIdx.x * (blockDim.x >> 5) + (t >> 5);
    const int r0   = warp * RPW;              // first row of this warp
    const float4* __restrict__ emb4 = reinterpret_cast<const float4*>(emb);

    float4 ev[RPW];
#pragma unroll
    for (int j = 0; j < RPW; ++j) {
        const int r = min(r0 + j, C - 1);     // clamp; store is guarded
        ev[j] = emb4[(size_t)r * (HDIM / 4) + lane];
    }

    float dot[RPW], esq[RPW];
#pragma unroll
    for (int j = 0; j < RPW; ++j) {
        dot[j] = ev[j].x * q4.x + ev[j].y * q4.y + ev[j].z * q4.z + ev[j].w * q4.w;
        esq[j] = ev[j].x * ev[j].x + ev[j].y * ev[j].y + ev[j].z * ev[j].z + ev[j].w * ev[j].w;
    }
#pragma unroll
    for (int o = 16; o; o >>= 1) {
#pragma unroll
        for (int j = 0; j < RPW; ++j) {
            dot[j] += __shfl_xor_sync(0xffffffffu, dot[j], o);
            esq[j] += __shfl_xor_sync(0xffffffffu, esq[j], o);
        }
    }

    if (lane < RPW) {
        const int r = r0 + lane;
        if (r < C)
            g_sims[r] = dot[lane] * rqn / fmaxf(sqrtf(esq[lane]), 1e-8f);
    }
}

// ---------------------------------------------------------------------------
// Kernel 2: stage-1 top-8 (PDL consumer: sync before reading g_sims).
// ---------------------------------------------------------------------------
__global__ void topk_stage1(int C) {
    __shared__ float sv[256 * KTOP];
    __shared__ int   si[256 * KTOP];
    const int t = threadIdx.x;

    cudaGridDependencySynchronize();          // wait for sims_kernel's stores

    float lv[KTOP]; int li[KTOP];
#pragma unroll
    for (int j = 0; j < KTOP; ++j) { lv[j] = -INFINITY; li[j] = INT_MAX; }

    for (int c = blockIdx.x * blockDim.x + t; c < C; c += gridDim.x * blockDim.x)
        insert_topk(lv, li, g_sims[c], c);

#pragma unroll
    for (int j = 0; j < KTOP; ++j) { sv[t * KTOP + j] = lv[j]; si[t * KTOP + j] = li[j]; }
    __syncthreads();
    block_merge_topk(sv, si);

    if (t < KTOP) {
        g_cand_v[blockIdx.x * KTOP + t] = sv[t];
        g_cand_i[blockIdx.x * KTOP + t] = si[t];
    }
}

// ---------------------------------------------------------------------------
// Kernel 3: merge 1024 candidates -> global top-8 (PDL consumer).
// ---------------------------------------------------------------------------
__global__ void topk_final(float* __restrict__ out) {
    __shared__ float sv[256 * KTOP];
    __shared__ int   si[256 * KTOP];
    const int t = threadIdx.x;

    cudaGridDependencySynchronize();          // wait for stage1's candidates

    float lv[KTOP]; int li[KTOP];
#pragma unroll
    for (int j = 0; j < KTOP; ++j) { lv[j] = -INFINITY; li[j] = INT_MAX; }

    for (int c = t; c < NB1 * KTOP; c += 256)
        insert_topk(lv, li, g_cand_v[c], g_cand_i[c]);

#pragma unroll
    for (int j = 0; j < KTOP; ++j) { sv[t * KTOP + j] = lv[j]; si[t * KTOP + j] = li[j]; }
    __syncthreads();
    block_merge_topk(sv, si);

    if (t < KTOP) {
        g_top_v[t] = sv[t];
        g_top_i[t] = si[t];
        out[KTOP * SDIM * HDIM + t] = sv[t];   // top_scores[0]
    }
}

// ---------------------------------------------------------------------------
// Kernel 4: gather top-8 episodes (PDL consumer).
// ---------------------------------------------------------------------------
__global__ void gather_kernel(const float* __restrict__ episodes,
                              float* __restrict__ out) {
    cudaGridDependencySynchronize();          // wait for topk_final's g_top_i

    const int e    = blockIdx.x >> 3;
    const int part = blockIdx.x & 7;
    const int idx  = g_top_i[e];

    const int per = (SDIM * HDIM / 4) / 8;    // 128 float4 per block
    const float4* __restrict__ src =
        reinterpret_cast<const float4*>(episodes + (size_t)idx * (SDIM * HDIM)) + part * per;
    float4* __restrict__ dst =
        reinterpret_cast<float4*>(out + (size_t)e * (SDIM * HDIM)) + part * per;

    if (threadIdx.x < per) dst[threadIdx.x] = src[threadIdx.x];
}

// Launch a kernel with programmatic stream serialization (PDL): the node is
// pre-launched while its predecessor still runs; data safety comes from the
// in-kernel cudaGridDependencySynchronize().
template <typename... Args>
static void launch_pdl(void (*kern)(Args...), dim3 grid, dim3 block, Args... args) {
    cudaLaunchConfig_t cfg = {};
    cfg.gridDim  = grid;
    cfg.blockDim = block;
    cfg.dynamicSmemBytes = 0;
    cfg.stream = 0;
    cudaLaunchAttribute attr[1];
    attr[0].id = cudaLaunchAttributeProgrammaticStreamSerialization;
    attr[0].val.programmaticStreamSerializationAllowed = 1;
    cfg.attrs = attr;
    cfg.numAttrs = 1;
    cudaLaunchKernelEx(&cfg, kern, args...);
}

extern "C" void kernel_launch(void* const* d_in, const int* in_sizes, int n_in,
                              void* d_out, int out_size) {
    const float* query    = (const float*)d_in[0];  // [B, 128]
    const float* episodes = (const float*)d_in[1];  // [C, 32, 128]
    const float* emb      = (const float*)d_in[2];  // [C, 128]
    (void)n_in; (void)out_size;

    const int C = in_sizes[2] / HDIM;               // 100000

    const int nwarps  = (C + RPW - 1) / RPW;        // 12500
    const int blocksA = (nwarps + 7) / 8;           // 1563
    sims_kernel<<<blocksA, 256>>>(query, emb, C);

    launch_pdl(topk_stage1, dim3(NB1), dim3(256), C);
    launch_pdl(topk_final, dim3(1), dim3(256), (float*)d_out);
    launch_pdl(gather_kernel, dim3(64), dim3(128),
               (const float*)episodes, (float*)d_out);
}